// round 14
// baseline (speedup 1.0000x reference)
#include <cuda_runtime.h>
#include <cuda_bf16.h>

#define NN 100000
#define EE 1600000
#define HH 128
#define GG 64
#define SCAN_BLKS ((NN + 255) / 256)   // 391

typedef unsigned long long u64;
typedef unsigned int u32;

// ------------- scratch (static device globals; no allocation) -------------
__device__ float  g_dinv[NN];
__device__ int    g_cnt[NN];
__device__ int    g_offs[NN + 1];
__device__ int    g_fill[NN];
__device__ int2   g_edge[EE];                 // (src_row, norm-as-int)
__device__ int    g_bsum[SCAN_BLKS];
__device__ int    g_bpre[SCAN_BLKS];
__device__ __nv_bfloat16 g_hwb[NN * HH];      // h @ W in bf16 (25.6 MB)
__device__ float  g_agg[NN * HH];             // aggregated output (fp32)
__device__ __nv_bfloat16 g_whiT[HH * HH];     // W^T hi part (bf16, [n][k])
__device__ __nv_bfloat16 g_wloT[HH * HH];     // W^T lo part (bf16, [n][k])
__device__ double g_sum[3][HH];
__device__ double g_sumsq[3][HH];
__device__ float  g_sc[3][HH];
__device__ float  g_sh[3][HH];
__device__ float  g_pool[GG * HH];
__device__ float  g_gcnt[GG];

__device__ __forceinline__ u32 smem_u32(const void* p) {
    u32 a;
    asm("{ .reg .u64 t; cvta.to.shared.u64 t, %1; cvt.u32.u64 %0, t; }" : "=r"(a) : "l"(p));
    return a;
}

// ------------- init / degree / CSR build -------------
__global__ void k_zero() {
    int i = blockIdx.x * blockDim.x + threadIdx.x;
    if (i < NN) { g_cnt[i] = 0; g_fill[i] = 0; }
    if (i < 3 * HH) { ((double*)g_sum)[i] = 0.0; ((double*)g_sumsq)[i] = 0.0; }
    if (i < GG * HH) g_pool[i] = 0.0f;
    if (i < GG) g_gcnt[i] = 0.0f;
}

__global__ void k_hist(const int* __restrict__ col) {
    int i = blockIdx.x * blockDim.x + threadIdx.x;
    if (i < EE) atomicAdd(&g_cnt[col[i]], 1);
}

__global__ void k_dinv() {
    int i = blockIdx.x * blockDim.x + threadIdx.x;
    if (i < NN) g_dinv[i] = rsqrtf((float)(g_cnt[i] + 1));
}

__global__ void k_scan1() {
    __shared__ int sh[256];
    int tid = threadIdx.x;
    int i = blockIdx.x * 256 + tid;
    int v = (i < NN) ? g_cnt[i] : 0;
    sh[tid] = v;
    __syncthreads();
#pragma unroll
    for (int off = 1; off < 256; off <<= 1) {
        int t = (tid >= off) ? sh[tid - off] : 0;
        __syncthreads();
        sh[tid] += t;
        __syncthreads();
    }
    if (i < NN) g_offs[i] = sh[tid] - v;
    if (tid == 255) g_bsum[blockIdx.x] = sh[255];
}

__global__ void k_scan2() {
    __shared__ int sh[SCAN_BLKS];
    int tid = threadIdx.x;
    for (int i = tid; i < SCAN_BLKS; i += blockDim.x) sh[i] = g_bsum[i];
    __syncthreads();
    if (tid == 0) {
        int run = 0;
        for (int i = 0; i < SCAN_BLKS; i++) { int t = sh[i]; sh[i] = run; run += t; }
    }
    __syncthreads();
    for (int i = tid; i < SCAN_BLKS; i += blockDim.x) g_bpre[i] = sh[i];
}

__global__ void k_scan3() {
    int i = blockIdx.x * 256 + threadIdx.x;
    if (i < NN) g_offs[i] += g_bpre[blockIdx.x];
    if (i == 0) g_offs[NN] = EE;
}

__global__ void k_fill(const int* __restrict__ row, const int* __restrict__ col) {
    int e = blockIdx.x * blockDim.x + threadIdx.x;
    if (e < EE) {
        int c = col[e];
        int r = row[e];
        int p = g_offs[c] + atomicAdd(&g_fill[c], 1);
        float nrm = g_dinv[r] * g_dinv[c];
        g_edge[p] = make_int2(r, __float_as_int(nrm));
    }
}

// ------------- W prep: transpose + hi/lo bf16 split -------------
__global__ void k_prepw(const float* __restrict__ W) {
    int idx = blockIdx.x * 256 + threadIdx.x;
    if (idx < HH * HH) {
        int k = idx >> 7, n = idx & 127;
        float w = W[idx];
        __nv_bfloat16 hi = __float2bfloat16(w);
        float rem = w - __bfloat162float(hi);
        g_whiT[n * HH + k] = hi;
        g_wloT[n * HH + k] = __float2bfloat16(rem);
    }
}

// ------------- GEMM: mma.sync bf16 (m16n8k16), W hi+lo accumulate -------------
// (round-11/13 proven version: x2 B ldmatrix, 80 regs, ~37us)
#define GEMM_SMEM (96 * 1024)

__global__ void __launch_bounds__(256) k_gemm(const float* __restrict__ Aext, int layer) {
    extern __shared__ unsigned char smem[];
    unsigned char* AsB = smem;
    unsigned char* WhB = smem + 32768;
    unsigned char* WlB = smem + 65536;
    const float* A = Aext ? Aext : g_agg;
    int tid = threadIdx.x, lane = tid & 31, wid = tid >> 5;
    int rowBase = blockIdx.x * 128;

    {
        const uint4* wh = (const uint4*)g_whiT;
        const uint4* wl = (const uint4*)g_wloT;
#pragma unroll
        for (int it = 0; it < 8; it++) {
            int i = tid + it * 256;
            int n = i >> 4, c = i & 15;
            u32 off = n * 256 + ((c ^ (n & 7)) << 4);
            *(uint4*)(WhB + off) = wh[i];
            *(uint4*)(WlB + off) = wl[i];
        }
    }
    {
#pragma unroll
        for (int it = 0; it < 8; it++) {
            int i = tid + it * 256;
            int r = i >> 4, c = i & 15;
            int row = rowBase + r;
            int k0 = c * 8;
            float v[8];
            if (row < NN) {
                float4 f0 = *(const float4*)&A[row * HH + k0];
                float4 f1 = *(const float4*)&A[row * HH + k0 + 4];
                v[0] = f0.x; v[1] = f0.y; v[2] = f0.z; v[3] = f0.w;
                v[4] = f1.x; v[5] = f1.y; v[6] = f1.z; v[7] = f1.w;
                if (layer > 0) {
                    int p = layer - 1;
#pragma unroll
                    for (int j = 0; j < 8; j++)
                        v[j] = fmaxf(fmaf(g_sc[p][k0 + j], v[j], g_sh[p][k0 + j]), 0.f);
                }
            } else {
#pragma unroll
                for (int j = 0; j < 8; j++) v[j] = 0.f;
            }
            u32 pk[4];
#pragma unroll
            for (int j = 0; j < 4; j++) {
                __nv_bfloat162 t = __float22bfloat162_rn(make_float2(v[2 * j], v[2 * j + 1]));
                pk[j] = *(u32*)&t;
            }
            u32 off = r * 256 + ((c ^ (r & 7)) << 4);
            *(uint4*)(AsB + off) = make_uint4(pk[0], pk[1], pk[2], pk[3]);
        }
    }
    __syncthreads();

    u32 asBase = smem_u32(AsB);
    u32 whBase = smem_u32(WhB);
    u32 wlBase = smem_u32(WlB);

    int r0 = wid * 16;
    float acc[16][4];
#pragma unroll
    for (int j = 0; j < 16; j++)
#pragma unroll
        for (int q = 0; q < 4; q++) acc[j][q] = 0.f;

    int amat = lane >> 3, ari = lane & 7;
    int arow = r0 + ((amat & 1) << 3) + ari;
    int achunkHi = amat >> 1;
    int bl = lane & 15;
    int bn_off = bl & 7;
    int bchunkHi = (bl >> 3) & 1;

#pragma unroll
    for (int ks = 0; ks < 8; ks++) {
        u32 a0, a1, a2, a3;
        {
            int chunk = 2 * ks + achunkHi;
            u32 addr = asBase + arow * 256 + ((chunk ^ (arow & 7)) << 4);
            asm volatile("ldmatrix.sync.aligned.m8n8.x4.shared.b16 {%0,%1,%2,%3}, [%4];"
                         : "=r"(a0), "=r"(a1), "=r"(a2), "=r"(a3) : "r"(addr));
        }
        int bchunk = 2 * ks + bchunkHi;
#pragma unroll
        for (int j = 0; j < 16; j++) {
            int n = j * 8 + bn_off;
            u32 soff = n * 256 + ((bchunk ^ (n & 7)) << 4);
            u32 b0, b1;
            asm volatile("ldmatrix.sync.aligned.m8n8.x2.shared.b16 {%0,%1}, [%2];"
                         : "=r"(b0), "=r"(b1) : "r"(whBase + soff));
            asm volatile("mma.sync.aligned.m16n8k16.row.col.f32.bf16.bf16.f32 "
                         "{%0,%1,%2,%3}, {%4,%5,%6,%7}, {%8,%9}, {%0,%1,%2,%3};"
                         : "+f"(acc[j][0]), "+f"(acc[j][1]), "+f"(acc[j][2]), "+f"(acc[j][3])
                         : "r"(a0), "r"(a1), "r"(a2), "r"(a3), "r"(b0), "r"(b1));
            asm volatile("ldmatrix.sync.aligned.m8n8.x2.shared.b16 {%0,%1}, [%2];"
                         : "=r"(b0), "=r"(b1) : "r"(wlBase + soff));
            asm volatile("mma.sync.aligned.m16n8k16.row.col.f32.bf16.bf16.f32 "
                         "{%0,%1,%2,%3}, {%4,%5,%6,%7}, {%8,%9}, {%0,%1,%2,%3};"
                         : "+f"(acc[j][0]), "+f"(acc[j][1]), "+f"(acc[j][2]), "+f"(acc[j][3])
                         : "r"(a0), "r"(a1), "r"(a2), "r"(a3), "r"(b0), "r"(b1));
        }
    }

    int rowA = rowBase + r0 + (lane >> 2);
    int rowB = rowA + 8;
    int colOff = 2 * (lane & 3);
#pragma unroll
    for (int j = 0; j < 16; j++) {
        int col = j * 8 + colOff;
        if (rowA < NN) {
            __nv_bfloat162 t = __float22bfloat162_rn(make_float2(acc[j][0], acc[j][1]));
            *(__nv_bfloat162*)&g_hwb[rowA * HH + col] = t;
        }
        if (rowB < NN) {
            __nv_bfloat162 t = __float22bfloat162_rn(make_float2(acc[j][2], acc[j][3]));
            *(__nv_bfloat162*)&g_hwb[rowB * HH + col] = t;
        }
    }
}

// 8-feature bf16 row segment FMA into fp32 accumulators
__device__ __forceinline__ void acc8_fma(float* a, uint4 v, float n) {
    float2 f;
    f = __bfloat1622float2(*reinterpret_cast<__nv_bfloat162*>(&v.x));
    a[0] = fmaf(n, f.x, a[0]); a[1] = fmaf(n, f.y, a[1]);
    f = __bfloat1622float2(*reinterpret_cast<__nv_bfloat162*>(&v.y));
    a[2] = fmaf(n, f.x, a[2]); a[3] = fmaf(n, f.y, a[3]);
    f = __bfloat1622float2(*reinterpret_cast<__nv_bfloat162*>(&v.z));
    a[4] = fmaf(n, f.x, a[4]); a[5] = fmaf(n, f.y, a[5]);
    f = __bfloat1622float2(*reinterpret_cast<__nv_bfloat162*>(&v.w));
    a[6] = fmaf(n, f.x, a[6]); a[7] = fmaf(n, f.y, a[7]);
}

// ------------- CSR aggregation: warp/node, edge-pair half-warps -------------
// lanes 0-15 process even edges, lanes 16-31 odd edges of the SAME node.
// Each lane owns 8 features (uint4 gather). Combine via shfl(16) at the end.
// grid = NN/16 = 6250 exactly; no node guards needed.
__global__ void __launch_bounds__(512) k_agg(const float* __restrict__ bias, int layer) {
    __shared__ float s_part[16][256];     // per warp: 128 sums | 128 sqsums
    int tid = threadIdx.x;
    int warp = tid >> 5, lane = tid & 31;
    int half = lane >> 4, l16 = lane & 15;
    int node = blockIdx.x * 16 + warp;
    int c0 = l16 * 8;

    float acc[8];
    if (half == 0) {
        float4 bb0 = *(const float4*)&bias[c0];
        float4 bb1 = *(const float4*)&bias[c0 + 4];
        float d = g_dinv[node];
        float s = d * d;
        uint4 h = *(const uint4*)&g_hwb[node * HH + c0];
        float2 f;
        f = __bfloat1622float2(*reinterpret_cast<__nv_bfloat162*>(&h.x));
        acc[0] = fmaf(s, f.x, bb0.x); acc[1] = fmaf(s, f.y, bb0.y);
        f = __bfloat1622float2(*reinterpret_cast<__nv_bfloat162*>(&h.y));
        acc[2] = fmaf(s, f.x, bb0.z); acc[3] = fmaf(s, f.y, bb0.w);
        f = __bfloat1622float2(*reinterpret_cast<__nv_bfloat162*>(&h.z));
        acc[4] = fmaf(s, f.x, bb1.x); acc[5] = fmaf(s, f.y, bb1.y);
        f = __bfloat1622float2(*reinterpret_cast<__nv_bfloat162*>(&h.w));
        acc[6] = fmaf(s, f.x, bb1.z); acc[7] = fmaf(s, f.y, bb1.w);
    } else {
#pragma unroll
        for (int j = 0; j < 8; j++) acc[j] = 0.f;
    }

    int e0 = g_offs[node];
    int cnt = g_offs[node + 1] - e0;
    int P = cnt >> 1;                     // full pairs
    int p = 0;
    // 4 pairs (8 edges) per iteration — all loads guaranteed valid
    for (; p + 4 <= P; p += 4) {
        int b = e0 + 2 * p + half;
        int2 r0 = g_edge[b];
        int2 r1 = g_edge[b + 2];
        int2 r2 = g_edge[b + 4];
        int2 r3 = g_edge[b + 6];
        uint4 v0 = *(const uint4*)&g_hwb[r0.x * HH + c0];
        uint4 v1 = *(const uint4*)&g_hwb[r1.x * HH + c0];
        uint4 v2 = *(const uint4*)&g_hwb[r2.x * HH + c0];
        uint4 v3 = *(const uint4*)&g_hwb[r3.x * HH + c0];
        acc8_fma(acc, v0, __int_as_float(r0.y));
        acc8_fma(acc, v1, __int_as_float(r1.y));
        acc8_fma(acc, v2, __int_as_float(r2.y));
        acc8_fma(acc, v3, __int_as_float(r3.y));
    }
    for (; p < P; p++) {
        int2 r = g_edge[e0 + 2 * p + half];
        uint4 v = *(const uint4*)&g_hwb[r.x * HH + c0];
        acc8_fma(acc, v, __int_as_float(r.y));
    }
    if ((cnt & 1) && half == 0) {         // odd tail edge -> half 0 only
        int2 r = g_edge[e0 + cnt - 1];
        uint4 v = *(const uint4*)&g_hwb[r.x * HH + c0];
        acc8_fma(acc, v, __int_as_float(r.y));
    }

    // combine halves
#pragma unroll
    for (int j = 0; j < 8; j++) acc[j] += __shfl_down_sync(0xFFFFFFFFu, acc[j], 16);

    if (half == 0) {
        *(float4*)&g_agg[node * HH + c0] = make_float4(acc[0], acc[1], acc[2], acc[3]);
        *(float4*)&g_agg[node * HH + c0 + 4] = make_float4(acc[4], acc[5], acc[6], acc[7]);
#pragma unroll
        for (int j = 0; j < 8; j++) {
            s_part[warp][c0 + j] = acc[j];
            s_part[warp][128 + c0 + j] = acc[j] * acc[j];
        }
    }
    __syncthreads();
    if (tid < 256) {
        float v = 0.f;
#pragma unroll
        for (int w = 0; w < 16; w++) v += s_part[w][tid];
        if (tid < 128) atomicAdd(&g_sum[layer][tid], (double)v);
        else atomicAdd(&g_sumsq[layer][tid - 128], (double)v);
    }
}

__global__ void k_finalize(int layer, const float* __restrict__ gam,
                           const float* __restrict__ bet) {
    int f = threadIdx.x;
    double mu = g_sum[layer][f] / (double)NN;
    double var = g_sumsq[layer][f] / (double)NN - mu * mu;
    float rstd = rsqrtf((float)var + 1e-5f);
    float sc = gam[f] * rstd;
    g_sc[layer][f] = sc;
    g_sh[layer][f] = bet[f] - (float)mu * sc;
}

// ------------- global mean pool -------------
#define POOL_CHUNK 128
__global__ void k_pool(const int* __restrict__ batch) {
    int f = threadIdx.x;
    int r0 = blockIdx.x * POOL_CHUNK;
    if (r0 >= NN) return;
    int rEnd = min(r0 + POOL_CHUNK, NN);
    float sc = g_sc[2][f], sh = g_sh[2][f];
    int gcur = batch[r0];
    float acc = 0.f;
    int cnt = 0;
    for (int r = r0; r < rEnd; r++) {
        int g = batch[r];
        if (g != gcur) {
            atomicAdd(&g_pool[gcur * HH + f], acc);
            if (f == 0) atomicAdd(&g_gcnt[gcur], (float)cnt);
            acc = 0.f; cnt = 0; gcur = g;
        }
        float v = fmaxf(fmaf(sc, g_agg[r * HH + f], sh), 0.f);
        acc += v;
        cnt++;
    }
    atomicAdd(&g_pool[gcur * HH + f], acc);
    if (f == 0) atomicAdd(&g_gcnt[gcur], (float)cnt);
}

// ------------- final FC -------------
__global__ void k_fc(const float* __restrict__ fw, const float* __restrict__ fb,
                     float* __restrict__ out) {
    __shared__ float P[GG * HH];
    int tid = threadIdx.x;
    for (int i = tid; i < GG * HH; i += 256) {
        float c = fmaxf(g_gcnt[i >> 7], 1.0f);
        P[i] = g_pool[i] / c;
    }
    __syncthreads();
    int g = tid >> 2;
    int o0 = (tid & 3) * 32;
    float acc[32];
#pragma unroll
    for (int j = 0; j < 32; j++) acc[j] = fb[o0 + j];
    for (int f = 0; f < HH; f++) {
        float p = P[g * HH + f];
#pragma unroll
        for (int j4 = 0; j4 < 8; j4++) {
            float4 w = *(const float4*)&fw[f * HH + o0 + j4 * 4];
            acc[j4 * 4 + 0] = fmaf(p, w.x, acc[j4 * 4 + 0]);
            acc[j4 * 4 + 1] = fmaf(p, w.y, acc[j4 * 4 + 1]);
            acc[j4 * 4 + 2] = fmaf(p, w.z, acc[j4 * 4 + 2]);
            acc[j4 * 4 + 3] = fmaf(p, w.w, acc[j4 * 4 + 3]);
        }
    }
#pragma unroll
    for (int j4 = 0; j4 < 8; j4++) {
        *(float4*)&out[g * HH + o0 + j4 * 4] =
            make_float4(acc[j4 * 4 + 0], acc[j4 * 4 + 1],
                        acc[j4 * 4 + 2], acc[j4 * 4 + 3]);
    }
}

// ------------- launch -------------
extern "C" void kernel_launch(void* const* d_in, const int* in_sizes, int n_in,
                              void* d_out, int out_size) {
    const float* x     = (const float*)d_in[0];
    const int*   ei    = (const int*)d_in[1];
    const int*   batch = (const int*)d_in[2];
    const float* W1 = (const float*)d_in[3];
    const float* b1 = (const float*)d_in[4];
    const float* g1 = (const float*)d_in[5];
    const float* be1 = (const float*)d_in[6];
    const float* W2 = (const float*)d_in[7];
    const float* b2 = (const float*)d_in[8];
    const float* g2 = (const float*)d_in[9];
    const float* be2 = (const float*)d_in[10];
    const float* W3 = (const float*)d_in[11];
    const float* b3 = (const float*)d_in[12];
    const float* g3 = (const float*)d_in[13];
    const float* be3 = (const float*)d_in[14];
    const float* fcw = (const float*)d_in[15];
    const float* fcb = (const float*)d_in[16];
    const int* erow = ei;
    const int* ecol = ei + EE;
    float* out = (float*)d_out;

    cudaFuncSetAttribute(k_gemm, cudaFuncAttributeMaxDynamicSharedMemorySize, GEMM_SMEM);

    const int gemmBlocks = (NN + 127) / 128;   // 782
    const int aggBlocks  = NN / 16;            // 6250 exactly

    // layer-1 GEMM stays 4th so the profiler capture lands on it.
    k_prepw<<<64, 256>>>(W1);
    k_zero<<<SCAN_BLKS, 256>>>();
    k_hist<<<(EE + 255) / 256, 256>>>(ecol);
    k_gemm<<<gemmBlocks, 256, GEMM_SMEM>>>(x, 0);
    k_dinv<<<SCAN_BLKS, 256>>>();
    k_scan1<<<SCAN_BLKS, 256>>>();
    k_scan2<<<1, 512>>>();
    k_scan3<<<SCAN_BLKS, 256>>>();
    k_fill<<<(EE + 255) / 256, 256>>>(erow, ecol);

    k_agg<<<aggBlocks, 512>>>(b1, 0);
    k_finalize<<<1, 128>>>(0, g1, be1);

    k_prepw<<<64, 256>>>(W2);
    k_gemm<<<gemmBlocks, 256, GEMM_SMEM>>>(nullptr, 1);
    k_agg<<<aggBlocks, 512>>>(b2, 1);
    k_finalize<<<1, 128>>>(1, g2, be2);

    k_prepw<<<64, 256>>>(W3);
    k_gemm<<<gemmBlocks, 256, GEMM_SMEM>>>(nullptr, 2);
    k_agg<<<aggBlocks, 512>>>(b3, 2);
    k_finalize<<<1, 128>>>(2, g3, be3);

    k_pool<<<(NN + POOL_CHUNK - 1) / POOL_CHUNK, 128>>>(batch);
    k_fc<<<1, 256>>>(fcw, fcb, out);
}

// round 15
// speedup vs baseline: 1.8536x; 1.8536x over previous
#include <cuda_runtime.h>
#include <cuda_bf16.h>

#define NN 100000
#define EE 1600000
#define HH 128
#define GG 64
#define SCAN_BLKS ((NN + 255) / 256)   // 391

typedef unsigned long long u64;
typedef unsigned int u32;

// ------------- scratch (static device globals; no allocation) -------------
__device__ float  g_dinv[NN];
__device__ int    g_cnt[NN];
__device__ int    g_offs[NN + 1];
__device__ int    g_fill[NN];
__device__ int2   g_edge[EE];                 // (src_row, norm-as-int)
__device__ int    g_bsum[SCAN_BLKS];
__device__ int    g_bpre[SCAN_BLKS];
__device__ __nv_bfloat16 g_hwb[NN * HH];      // h @ W in bf16 (25.6 MB)
__device__ __nv_bfloat16 g_aggb[NN * HH];     // aggregated output in bf16 (25.6 MB)
__device__ __nv_bfloat16 g_whiT[HH * HH];     // W^T hi part (bf16, [n][k])
__device__ __nv_bfloat16 g_wloT[HH * HH];     // W^T lo part (bf16, [n][k])
__device__ double g_sum[3][HH];
__device__ double g_sumsq[3][HH];
__device__ float  g_sc[3][HH];
__device__ float  g_sh[3][HH];
__device__ float  g_pool[GG * HH];
__device__ float  g_gcnt[GG];

__device__ __forceinline__ u32 smem_u32(const void* p) {
    u32 a;
    asm("{ .reg .u64 t; cvta.to.shared.u64 t, %1; cvt.u32.u64 %0, t; }" : "=r"(a) : "l"(p));
    return a;
}

// ------------- init / degree / CSR build -------------
__global__ void k_zero() {
    int i = blockIdx.x * blockDim.x + threadIdx.x;
    if (i < NN) { g_cnt[i] = 0; g_fill[i] = 0; }
    if (i < 3 * HH) { ((double*)g_sum)[i] = 0.0; ((double*)g_sumsq)[i] = 0.0; }
    if (i < GG * HH) g_pool[i] = 0.0f;
    if (i < GG) g_gcnt[i] = 0.0f;
}

__global__ void k_hist(const int* __restrict__ col) {
    int i = blockIdx.x * blockDim.x + threadIdx.x;
    if (i < EE) atomicAdd(&g_cnt[col[i]], 1);
}

__global__ void k_dinv() {
    int i = blockIdx.x * blockDim.x + threadIdx.x;
    if (i < NN) g_dinv[i] = rsqrtf((float)(g_cnt[i] + 1));
}

__global__ void k_scan1() {
    __shared__ int sh[256];
    int tid = threadIdx.x;
    int i = blockIdx.x * 256 + tid;
    int v = (i < NN) ? g_cnt[i] : 0;
    sh[tid] = v;
    __syncthreads();
#pragma unroll
    for (int off = 1; off < 256; off <<= 1) {
        int t = (tid >= off) ? sh[tid - off] : 0;
        __syncthreads();
        sh[tid] += t;
        __syncthreads();
    }
    if (i < NN) g_offs[i] = sh[tid] - v;
    if (tid == 255) g_bsum[blockIdx.x] = sh[255];
}

__global__ void k_scan2() {
    __shared__ int sh[SCAN_BLKS];
    int tid = threadIdx.x;
    for (int i = tid; i < SCAN_BLKS; i += blockDim.x) sh[i] = g_bsum[i];
    __syncthreads();
    if (tid == 0) {
        int run = 0;
        for (int i = 0; i < SCAN_BLKS; i++) { int t = sh[i]; sh[i] = run; run += t; }
    }
    __syncthreads();
    for (int i = tid; i < SCAN_BLKS; i += blockDim.x) g_bpre[i] = sh[i];
}

__global__ void k_scan3() {
    int i = blockIdx.x * 256 + threadIdx.x;
    if (i < NN) g_offs[i] += g_bpre[blockIdx.x];
    if (i == 0) g_offs[NN] = EE;
}

__global__ void k_fill(const int* __restrict__ row, const int* __restrict__ col) {
    int e = blockIdx.x * blockDim.x + threadIdx.x;
    if (e < EE) {
        int c = col[e];
        int r = row[e];
        int p = g_offs[c] + atomicAdd(&g_fill[c], 1);
        float nrm = g_dinv[r] * g_dinv[c];
        g_edge[p] = make_int2(r, __float_as_int(nrm));
    }
}

// ------------- W prep: transpose + hi/lo bf16 split -------------
__global__ void k_prepw(const float* __restrict__ W) {
    int idx = blockIdx.x * 256 + threadIdx.x;
    if (idx < HH * HH) {
        int k = idx >> 7, n = idx & 127;
        float w = W[idx];
        __nv_bfloat16 hi = __float2bfloat16(w);
        float rem = w - __bfloat162float(hi);
        g_whiT[n * HH + k] = hi;
        g_wloT[n * HH + k] = __float2bfloat16(rem);
    }
}

// ------------- GEMM: mma.sync bf16, warp-per-N-slice mainloop -------------
// smem: As[128][128] bf16 (32KB) | Wh (32KB) | Wl (32KB), chunk^(row&7) swizzle
// Each warp owns a 16-column slice for all 128 rows:
//   per k-step: 2 B ldmatrix.x4 (hi+lo) + 8 A ldmatrix.x4 + 32 MMA  (10 LDSM / 32 MMA)
#define GEMM_SMEM (96 * 1024)

__global__ void __launch_bounds__(256) k_gemm(const float* __restrict__ Aext, int layer) {
    extern __shared__ unsigned char smem[];
    unsigned char* AsB = smem;
    unsigned char* WhB = smem + 32768;
    unsigned char* WlB = smem + 65536;
    int tid = threadIdx.x, lane = tid & 31, wid = tid >> 5;
    int rowBase = blockIdx.x * 128;

    // --- load W hi/lo tiles ---
    {
        const uint4* wh = (const uint4*)g_whiT;
        const uint4* wl = (const uint4*)g_wloT;
#pragma unroll
        for (int it = 0; it < 8; it++) {
            int i = tid + it * 256;
            int n = i >> 4, c = i & 15;
            u32 off = n * 256 + ((c ^ (n & 7)) << 4);
            *(uint4*)(WhB + off) = wh[i];
            *(uint4*)(WlB + off) = wl[i];
        }
    }
    // --- load A tile -> (BN+ReLU) -> bf16, swizzled ---
    {
#pragma unroll
        for (int it = 0; it < 8; it++) {
            int i = tid + it * 256;
            int r = i >> 4, c = i & 15;
            int row = rowBase + r;
            int k0 = c * 8;
            float v[8];
            if (row < NN) {
                if (layer > 0) {
                    uint4 raw = *(const uint4*)&g_aggb[row * HH + k0];
                    float2 f;
                    f = __bfloat1622float2(*reinterpret_cast<__nv_bfloat162*>(&raw.x));
                    v[0] = f.x; v[1] = f.y;
                    f = __bfloat1622float2(*reinterpret_cast<__nv_bfloat162*>(&raw.y));
                    v[2] = f.x; v[3] = f.y;
                    f = __bfloat1622float2(*reinterpret_cast<__nv_bfloat162*>(&raw.z));
                    v[4] = f.x; v[5] = f.y;
                    f = __bfloat1622float2(*reinterpret_cast<__nv_bfloat162*>(&raw.w));
                    v[6] = f.x; v[7] = f.y;
                    int p = layer - 1;
#pragma unroll
                    for (int j = 0; j < 8; j++)
                        v[j] = fmaxf(fmaf(g_sc[p][k0 + j], v[j], g_sh[p][k0 + j]), 0.f);
                } else {
                    float4 f0 = *(const float4*)&Aext[row * HH + k0];
                    float4 f1 = *(const float4*)&Aext[row * HH + k0 + 4];
                    v[0] = f0.x; v[1] = f0.y; v[2] = f0.z; v[3] = f0.w;
                    v[4] = f1.x; v[5] = f1.y; v[6] = f1.z; v[7] = f1.w;
                }
            } else {
#pragma unroll
                for (int j = 0; j < 8; j++) v[j] = 0.f;
            }
            u32 pk[4];
#pragma unroll
            for (int j = 0; j < 4; j++) {
                __nv_bfloat162 t = __float22bfloat162_rn(make_float2(v[2 * j], v[2 * j + 1]));
                pk[j] = *(u32*)&t;
            }
            u32 off = r * 256 + ((c ^ (r & 7)) << 4);
            *(uint4*)(AsB + off) = make_uint4(pk[0], pk[1], pk[2], pk[3]);
        }
    }
    __syncthreads();

    u32 asBase = smem_u32(AsB);
    u32 whBase = smem_u32(WhB);
    u32 wlBase = smem_u32(WlB);

    int nbase = wid * 16;
    float acc[8][8];    // [mtile][ntile*4 + q]
#pragma unroll
    for (int i = 0; i < 8; i++)
#pragma unroll
        for (int q = 0; q < 8; q++) acc[i][q] = 0.f;

    // per-lane invariants
    int arbase = (((lane >> 3) & 1) << 3) + (lane & 7);   // A row-within-mtile
    int ach = lane >> 4;                                   // A k-half
    int bnrow = nbase + (((lane >> 4)) << 3) + (lane & 7); // B n-row (x4: 2 n-tiles)
    int bch = (lane >> 3) & 1;                             // B k-half

#pragma unroll
    for (int ks = 0; ks < 8; ks++) {
        int bchunk = 2 * ks + bch;
        u32 bsoff = bnrow * 256 + ((bchunk ^ (bnrow & 7)) << 4);
        u32 bh0, bh1, bh2, bh3, bl0, bl1, bl2, bl3;
        asm volatile("ldmatrix.sync.aligned.m8n8.x4.shared.b16 {%0,%1,%2,%3}, [%4];"
                     : "=r"(bh0), "=r"(bh1), "=r"(bh2), "=r"(bh3) : "r"(whBase + bsoff));
        asm volatile("ldmatrix.sync.aligned.m8n8.x4.shared.b16 {%0,%1,%2,%3}, [%4];"
                     : "=r"(bl0), "=r"(bl1), "=r"(bl2), "=r"(bl3) : "r"(wlBase + bsoff));
        int achunk = 2 * ks + ach;
#pragma unroll
        for (int i = 0; i < 8; i++) {
            int arow = i * 16 + arbase;
            u32 aaddr = asBase + arow * 256 + ((achunk ^ (arow & 7)) << 4);
            u32 a0, a1, a2, a3;
            asm volatile("ldmatrix.sync.aligned.m8n8.x4.shared.b16 {%0,%1,%2,%3}, [%4];"
                         : "=r"(a0), "=r"(a1), "=r"(a2), "=r"(a3) : "r"(aaddr));
            asm volatile("mma.sync.aligned.m16n8k16.row.col.f32.bf16.bf16.f32 "
                         "{%0,%1,%2,%3}, {%4,%5,%6,%7}, {%8,%9}, {%0,%1,%2,%3};"
                         : "+f"(acc[i][0]), "+f"(acc[i][1]), "+f"(acc[i][2]), "+f"(acc[i][3])
                         : "r"(a0), "r"(a1), "r"(a2), "r"(a3), "r"(bh0), "r"(bh1));
            asm volatile("mma.sync.aligned.m16n8k16.row.col.f32.bf16.bf16.f32 "
                         "{%0,%1,%2,%3}, {%4,%5,%6,%7}, {%8,%9}, {%0,%1,%2,%3};"
                         : "+f"(acc[i][4]), "+f"(acc[i][5]), "+f"(acc[i][6]), "+f"(acc[i][7])
                         : "r"(a0), "r"(a1), "r"(a2), "r"(a3), "r"(bh2), "r"(bh3));
            asm volatile("mma.sync.aligned.m16n8k16.row.col.f32.bf16.bf16.f32 "
                         "{%0,%1,%2,%3}, {%4,%5,%6,%7}, {%8,%9}, {%0,%1,%2,%3};"
                         : "+f"(acc[i][0]), "+f"(acc[i][1]), "+f"(acc[i][2]), "+f"(acc[i][3])
                         : "r"(a0), "r"(a1), "r"(a2), "r"(a3), "r"(bl0), "r"(bl1));
            asm volatile("mma.sync.aligned.m16n8k16.row.col.f32.bf16.bf16.f32 "
                         "{%0,%1,%2,%3}, {%4,%5,%6,%7}, {%8,%9}, {%0,%1,%2,%3};"
                         : "+f"(acc[i][4]), "+f"(acc[i][5]), "+f"(acc[i][6]), "+f"(acc[i][7])
                         : "r"(a0), "r"(a1), "r"(a2), "r"(a3), "r"(bl2), "r"(bl3));
        }
    }

    // --- epilogue: fp32 acc -> bf16 g_hwb (warp writes its 16-col slice) ---
    int rquad = lane >> 2;
    int coff = 2 * (lane & 3);
#pragma unroll
    for (int i = 0; i < 8; i++) {
        int rowA = rowBase + i * 16 + rquad;
        int rowB = rowA + 8;
#pragma unroll
        for (int j = 0; j < 2; j++) {
            int col = nbase + j * 8 + coff;
            if (rowA < NN) {
                __nv_bfloat162 t = __float22bfloat162_rn(
                    make_float2(acc[i][j * 4 + 0], acc[i][j * 4 + 1]));
                *(__nv_bfloat162*)&g_hwb[rowA * HH + col] = t;
            }
            if (rowB < NN) {
                __nv_bfloat162 t = __float22bfloat162_rn(
                    make_float2(acc[i][j * 4 + 2], acc[i][j * 4 + 3]));
                *(__nv_bfloat162*)&g_hwb[rowB * HH + col] = t;
            }
        }
    }
}

__device__ __forceinline__ void bf4_to_f4(uint2 raw, float4& out) {
    float2 f01 = __bfloat1622float2(*reinterpret_cast<__nv_bfloat162*>(&raw.x));
    float2 f23 = __bfloat1622float2(*reinterpret_cast<__nv_bfloat162*>(&raw.y));
    out = make_float4(f01.x, f01.y, f23.x, f23.y);
}

// ------------- CSR aggregation: warp/node (R13 proven), bf16 output -------------
__global__ void __launch_bounds__(512) k_agg(const float* __restrict__ bias, int layer) {
    __shared__ float s_part[16][256];     // per warp: 128 sums | 128 sqsums
    int tid = threadIdx.x;
    int warp = tid >> 5, lane = tid & 31;
    int node = blockIdx.x * 16 + warp;
    int c0 = lane * 4;

    float4 acc = make_float4(0.f, 0.f, 0.f, 0.f);
    if (node < NN) {
        float4 bb = *(const float4*)&bias[c0];
        float d = g_dinv[node];
        float s = d * d;
        float4 v0; bf4_to_f4(*(const uint2*)&g_hwb[node * HH + c0], v0);
        acc = make_float4(fmaf(s, v0.x, bb.x), fmaf(s, v0.y, bb.y),
                          fmaf(s, v0.z, bb.z), fmaf(s, v0.w, bb.w));
        int e = g_offs[node];
        int eEnd = g_offs[node + 1];
        int stop = e + ((eEnd - e) & ~3);
        for (; e < stop; e += 4) {
            int2 d0 = g_edge[e + 0];
            int2 d1 = g_edge[e + 1];
            int2 d2 = g_edge[e + 2];
            int2 d3 = g_edge[e + 3];
            uint2 r0 = *(const uint2*)&g_hwb[d0.x * HH + c0];
            uint2 r1 = *(const uint2*)&g_hwb[d1.x * HH + c0];
            uint2 r2 = *(const uint2*)&g_hwb[d2.x * HH + c0];
            uint2 r3 = *(const uint2*)&g_hwb[d3.x * HH + c0];
            float4 w0, w1, w2, w3;
            bf4_to_f4(r0, w0); bf4_to_f4(r1, w1);
            bf4_to_f4(r2, w2); bf4_to_f4(r3, w3);
            float n0 = __int_as_float(d0.y), n1 = __int_as_float(d1.y);
            float n2 = __int_as_float(d2.y), n3 = __int_as_float(d3.y);
            acc.x = fmaf(n0, w0.x, acc.x); acc.y = fmaf(n0, w0.y, acc.y);
            acc.z = fmaf(n0, w0.z, acc.z); acc.w = fmaf(n0, w0.w, acc.w);
            acc.x = fmaf(n1, w1.x, acc.x); acc.y = fmaf(n1, w1.y, acc.y);
            acc.z = fmaf(n1, w1.z, acc.z); acc.w = fmaf(n1, w1.w, acc.w);
            acc.x = fmaf(n2, w2.x, acc.x); acc.y = fmaf(n2, w2.y, acc.y);
            acc.z = fmaf(n2, w2.z, acc.z); acc.w = fmaf(n2, w2.w, acc.w);
            acc.x = fmaf(n3, w3.x, acc.x); acc.y = fmaf(n3, w3.y, acc.y);
            acc.z = fmaf(n3, w3.z, acc.z); acc.w = fmaf(n3, w3.w, acc.w);
        }
        for (; e < eEnd; e++) {
            int2 ed = g_edge[e];
            float4 v; bf4_to_f4(*(const uint2*)&g_hwb[ed.x * HH + c0], v);
            float nrm = __int_as_float(ed.y);
            acc.x = fmaf(nrm, v.x, acc.x);
            acc.y = fmaf(nrm, v.y, acc.y);
            acc.z = fmaf(nrm, v.z, acc.z);
            acc.w = fmaf(nrm, v.w, acc.w);
        }
        // store bf16 (consumers: next GEMM A-loader, pool — both convert anyway)
        __nv_bfloat162 t0 = __float22bfloat162_rn(make_float2(acc.x, acc.y));
        __nv_bfloat162 t1 = __float22bfloat162_rn(make_float2(acc.z, acc.w));
        uint2 st; st.x = *(u32*)&t0; st.y = *(u32*)&t1;
        *(uint2*)&g_aggb[node * HH + c0] = st;
    }
    // stats: fp32, pre-quantization; no collisions -> slab, no atomics
    s_part[warp][c0 + 0] = acc.x;
    s_part[warp][c0 + 1] = acc.y;
    s_part[warp][c0 + 2] = acc.z;
    s_part[warp][c0 + 3] = acc.w;
    s_part[warp][128 + c0 + 0] = acc.x * acc.x;
    s_part[warp][128 + c0 + 1] = acc.y * acc.y;
    s_part[warp][128 + c0 + 2] = acc.z * acc.z;
    s_part[warp][128 + c0 + 3] = acc.w * acc.w;
    __syncthreads();
    if (tid < 256) {
        float v = 0.f;
#pragma unroll
        for (int w = 0; w < 16; w++) v += s_part[w][tid];
        if (tid < 128) atomicAdd(&g_sum[layer][tid], (double)v);
        else atomicAdd(&g_sumsq[layer][tid - 128], (double)v);
    }
}

__global__ void k_finalize(int layer, const float* __restrict__ gam,
                           const float* __restrict__ bet) {
    int f = threadIdx.x;
    double mu = g_sum[layer][f] / (double)NN;
    double var = g_sumsq[layer][f] / (double)NN - mu * mu;
    float rstd = rsqrtf((float)var + 1e-5f);
    float sc = gam[f] * rstd;
    g_sc[layer][f] = sc;
    g_sh[layer][f] = bet[f] - (float)mu * sc;
}

// ------------- global mean pool (reads bf16 agg) -------------
#define POOL_CHUNK 128
__global__ void k_pool(const int* __restrict__ batch) {
    int f = threadIdx.x;
    int r0 = blockIdx.x * POOL_CHUNK;
    if (r0 >= NN) return;
    int rEnd = min(r0 + POOL_CHUNK, NN);
    float sc = g_sc[2][f], sh = g_sh[2][f];
    int gcur = batch[r0];
    float acc = 0.f;
    int cnt = 0;
    for (int r = r0; r < rEnd; r++) {
        int g = batch[r];
        if (g != gcur) {
            atomicAdd(&g_pool[gcur * HH + f], acc);
            if (f == 0) atomicAdd(&g_gcnt[gcur], (float)cnt);
            acc = 0.f; cnt = 0; gcur = g;
        }
        float v = fmaxf(fmaf(sc, __bfloat162float(g_aggb[r * HH + f]), sh), 0.f);
        acc += v;
        cnt++;
    }
    atomicAdd(&g_pool[gcur * HH + f], acc);
    if (f == 0) atomicAdd(&g_gcnt[gcur], (float)cnt);
}

// ------------- final FC -------------
__global__ void k_fc(const float* __restrict__ fw, const float* __restrict__ fb,
                     float* __restrict__ out) {
    __shared__ float P[GG * HH];
    int tid = threadIdx.x;
    for (int i = tid; i < GG * HH; i += 256) {
        float c = fmaxf(g_gcnt[i >> 7], 1.0f);
        P[i] = g_pool[i] / c;
    }
    __syncthreads();
    int g = tid >> 2;
    int o0 = (tid & 3) * 32;
    float acc[32];
#pragma unroll
    for (int j = 0; j < 32; j++) acc[j] = fb[o0 + j];
    for (int f = 0; f < HH; f++) {
        float p = P[g * HH + f];
#pragma unroll
        for (int j4 = 0; j4 < 8; j4++) {
            float4 w = *(const float4*)&fw[f * HH + o0 + j4 * 4];
            acc[j4 * 4 + 0] = fmaf(p, w.x, acc[j4 * 4 + 0]);
            acc[j4 * 4 + 1] = fmaf(p, w.y, acc[j4 * 4 + 1]);
            acc[j4 * 4 + 2] = fmaf(p, w.z, acc[j4 * 4 + 2]);
            acc[j4 * 4 + 3] = fmaf(p, w.w, acc[j4 * 4 + 3]);
        }
    }
#pragma unroll
    for (int j4 = 0; j4 < 8; j4++) {
        *(float4*)&out[g * HH + o0 + j4 * 4] =
            make_float4(acc[j4 * 4 + 0], acc[j4 * 4 + 1],
                        acc[j4 * 4 + 2], acc[j4 * 4 + 3]);
    }
}

// ------------- launch -------------
extern "C" void kernel_launch(void* const* d_in, const int* in_sizes, int n_in,
                              void* d_out, int out_size) {
    const float* x     = (const float*)d_in[0];
    const int*   ei    = (const int*)d_in[1];
    const int*   batch = (const int*)d_in[2];
    const float* W1 = (const float*)d_in[3];
    const float* b1 = (const float*)d_in[4];
    const float* g1 = (const float*)d_in[5];
    const float* be1 = (const float*)d_in[6];
    const float* W2 = (const float*)d_in[7];
    const float* b2 = (const float*)d_in[8];
    const float* g2 = (const float*)d_in[9];
    const float* be2 = (const float*)d_in[10];
    const float* W3 = (const float*)d_in[11];
    const float* b3 = (const float*)d_in[12];
    const float* g3 = (const float*)d_in[13];
    const float* be3 = (const float*)d_in[14];
    const float* fcw = (const float*)d_in[15];
    const float* fcb = (const float*)d_in[16];
    const int* erow = ei;
    const int* ecol = ei + EE;
    float* out = (float*)d_out;

    cudaFuncSetAttribute(k_gemm, cudaFuncAttributeMaxDynamicSharedMemorySize, GEMM_SMEM);

    const int gemmBlocks = (NN + 127) / 128;   // 782
    const int aggBlocks  = (NN + 15) / 16;     // 6250

    // layer-1 GEMM stays 4th so the profiler capture lands on it.
    k_prepw<<<64, 256>>>(W1);
    k_zero<<<SCAN_BLKS, 256>>>();
    k_hist<<<(EE + 255) / 256, 256>>>(ecol);
    k_gemm<<<gemmBlocks, 256, GEMM_SMEM>>>(x, 0);
    k_dinv<<<SCAN_BLKS, 256>>>();
    k_scan1<<<SCAN_BLKS, 256>>>();
    k_scan2<<<1, 512>>>();
    k_scan3<<<SCAN_BLKS, 256>>>();
    k_fill<<<(EE + 255) / 256, 256>>>(erow, ecol);

    k_agg<<<aggBlocks, 512>>>(b1, 0);
    k_finalize<<<1, 128>>>(0, g1, be1);

    k_prepw<<<64, 256>>>(W2);
    k_gemm<<<gemmBlocks, 256, GEMM_SMEM>>>(x, 1);
    k_agg<<<aggBlocks, 512>>>(b2, 1);
    k_finalize<<<1, 128>>>(1, g2, be2);

    k_prepw<<<64, 256>>>(W3);
    k_gemm<<<gemmBlocks, 256, GEMM_SMEM>>>(x, 2);
    k_agg<<<aggBlocks, 512>>>(b3, 2);
    k_finalize<<<1, 128>>>(2, g3, be3);

    k_pool<<<(NN + POOL_CHUNK - 1) / POOL_CHUNK, 128>>>(batch);
    k_fc<<<1, 256>>>(fcw, fcb, out);
}